// round 3
// baseline (speedup 1.0000x reference)
#include <cuda_runtime.h>
#include <math_constants.h>
#include <cstdint>

// Problem constants (fixed shapes from the reference)
constexpr int kB = 2;
constexpr int kC = 32;
constexpr int kH = 32;
constexpr int kW = 256;
constexpr int kN = kH * kW;            // 8192 points per batch
constexpr int kNX = 440;
constexpr int kNY = 500;
constexpr int kNVOX = kNX * kNY;       // 220000
constexpr float PCR0 = 0.0f, PCR1 = -40.0f, PCR2 = -3.0f, PCR5 = 1.0f;
constexpr float VOXS = 0.16f;

constexpr int TILE = 2048;             // candidates per smem tile (32 KB)

// Scratch (allocation-free: __device__ globals)
__device__ float4 g_near[kB * kN];     // compacted valid near pts: x,y,z, bitcast(orig idx)
__device__ float4 g_far [kB * kN];     // compacted valid far pts
__device__ int    g_ncnt[kB];
__device__ int    g_fcnt[kB];
__device__ float  g_cnt [kB * kNVOX];  // per-voxel point counts

// ---------------------------------------------------------------------------
// 1) zero output sums + counts (pure streaming stores)
// ---------------------------------------------------------------------------
__global__ void k_zero(float* __restrict__ out) {
    const int total  = (kB * kC * kNVOX) / 4;  // 3,520,000 float4
    const int ctotal = (kB * kNVOX) / 4;       //   110,000 float4
    float4 z = make_float4(0.f, 0.f, 0.f, 0.f);
    for (int i = blockIdx.x * blockDim.x + threadIdx.x; i < total + ctotal;
         i += gridDim.x * blockDim.x) {
        if (i < total) reinterpret_cast<float4*>(out)[i] = z;
        else           reinterpret_cast<float4*>(g_cnt)[i - total] = z;
    }
}

// ---------------------------------------------------------------------------
// 2) deterministic compaction (shuffle-based two-level scan)
// ---------------------------------------------------------------------------
__device__ __forceinline__ void compact_one(const float* __restrict__ p,
                                            const int* __restrict__ mm,
                                            float4* __restrict__ dst,
                                            int* __restrict__ cnt_out) {
    const int t = threadIdx.x;
    const int lane = t & 31, w = t >> 5;
    constexpr int PER = kN / 256;  // 32 elements per thread
    __shared__ int wsum[8];

    int c = 0;
#pragma unroll
    for (int k = 0; k < PER; ++k) c += (mm[t * PER + k] > 0);

    // inclusive warp scan
    int inc = c;
#pragma unroll
    for (int off = 1; off < 32; off <<= 1) {
        int n = __shfl_up_sync(0xFFFFFFFFu, inc, off);
        if (lane >= off) inc += n;
    }
    if (lane == 31) wsum[w] = inc;
    __syncthreads();
    if (t < 8) {
        int v = wsum[t];
        int p2 = v;
#pragma unroll
        for (int off = 1; off < 8; off <<= 1) {
            int n = __shfl_up_sync(0xFFu, p2, off);
            if (t >= off) p2 += n;
        }
        wsum[t] = p2 - v;              // exclusive
        if (t == 7) *cnt_out = p2;     // total
    }
    __syncthreads();
    int off = wsum[w] + inc - c;       // exclusive offset for this thread

    for (int k = 0; k < PER; ++k) {
        int n = t * PER + k;
        if (mm[n] > 0) {
            dst[off] = make_float4(p[n], p[kN + n], p[2 * kN + n],
                                   __int_as_float(n));
            ++off;
        }
    }
}

__global__ void k_compact(const float* __restrict__ pts,
                          const float* __restrict__ ptsf,
                          const int* __restrict__ m,
                          const int* __restrict__ mf) {
    const int b = blockIdx.x;
    compact_one(pts  + (size_t)b * 4 * kN, m  + (size_t)b * kN,
                &g_near[(size_t)b * kN], &g_ncnt[b]);
    __syncthreads();
    compact_one(ptsf + (size_t)b * 4 * kN, mf + (size_t)b * kN,
                &g_far[(size_t)b * kN], &g_fcnt[b]);
}

// ---------------------------------------------------------------------------
// 3) scatter valid near points into output sums + counts
// ---------------------------------------------------------------------------
__global__ void k_scatter_near(const float* __restrict__ fv,
                               const float* __restrict__ pts,
                               const int* __restrict__ m,
                               float* __restrict__ out) {
    int idx = blockIdx.x * blockDim.x + threadIdx.x;
    if (idx >= kB * kN) return;
    int b = idx / kN, n = idx % kN;
    if (m[(size_t)b * kN + n] <= 0) return;
    const float* p = pts + (size_t)b * 4 * kN;
    float x = p[n], y = p[kN + n], z = p[2 * kN + n];
    int ix = (int)floorf((x - PCR0) / VOXS);
    int iy = (int)floorf((y - PCR1) / VOXS);
    if (ix < 0 || ix >= kNX || iy < 0 || iy >= kNY || z < PCR2 || z >= PCR5) return;
    int seg = iy * kNX + ix;
    float* ob = out + (size_t)b * kC * kNVOX + seg;
    const float* f = fv + (size_t)b * kC * kN + n;
#pragma unroll
    for (int c = 0; c < kC; ++c) atomicAdd(ob + (size_t)c * kNVOX, f[(size_t)c * kN]);
    atomicAdd(&g_cnt[(size_t)b * kNVOX + seg], 1.0f);
}

// ---------------------------------------------------------------------------
// 4) 3-NN + interpolation + scatter. 4 lanes per far point; candidates in
//    smem as (x,y,z,|p|^2); hot loop = 3 FMA/pair with broadcast LDS.
//    Winners' distances recomputed exactly at the end.
// ---------------------------------------------------------------------------
__device__ __forceinline__ void insert3v(float dd, int v,
                                         float& l0, float& l1, float& l2,
                                         int& v0, int& v1, int& v2) {
    if (dd < l2) {
        if (dd < l1) {
            l2 = l1; v2 = v1;
            if (dd < l0) { l1 = l0; v1 = v0; l0 = dd; v0 = v; }
            else         { l1 = dd; v1 = v; }
        } else { l2 = dd; v2 = v; }
    }
}

__global__ void __launch_bounds__(256) k_nn(const float* __restrict__ fv,
                                            float* __restrict__ out) {
    __shared__ float4 sp[TILE];

    const int s   = threadIdx.x & 3;                 // sublane 0..3
    const int sub = threadIdx.x >> 2;                // subgroup in block 0..63
    const int b   = blockIdx.x >> 7;                 // 128 blocks per batch
    const int r   = (blockIdx.x & 127) * 64 + sub;   // far slot within batch

    const int fcnt = g_fcnt[b];
    if ((blockIdx.x & 127) * 64 >= fcnt) return;     // whole block idle
    const bool active = (r < fcnt);

    float4 fp = g_far[(size_t)b * kN + (active ? r : 0)];
    const float fx = fp.x, fy = fp.y, fz = fp.z;
    const float f2x = -2.0f * fx, f2y = -2.0f * fy, f2z = -2.0f * fz;

    const int V = g_ncnt[b];
    const float4* __restrict__ vp = &g_near[(size_t)b * kN];

    // lane-local top-3 on dd' = |p|^2 - 2 p.f  (ordering-equivalent to d^2)
    float l0 = CUDART_INF_F, l1 = CUDART_INF_F, l2 = CUDART_INF_F;
    int   v0 = 0x7FFFFFFF,   v1 = 0x7FFFFFFF,   v2 = 0x7FFFFFFF;

    for (int base = 0; base < V; base += TILE) {
        // cooperative tile fill; w-slot holds |p|^2; sentinel q=INF
#pragma unroll
        for (int i = threadIdx.x; i < TILE; i += 256) {
            int v = base + i;
            float4 p;
            if (v < V) {
                p = vp[v];
                p.w = fmaf(p.x, p.x, fmaf(p.y, p.y, p.z * p.z));
            } else {
                p = make_float4(0.f, 0.f, 0.f, CUDART_INF_F);
            }
            sp[i] = p;
        }
        __syncthreads();

        if (active) {
#pragma unroll 2
            for (int k = 0; k < TILE; k += 16) {
                float4 p0 = sp[k + s];
                float4 p1 = sp[k + s + 4];
                float4 p2 = sp[k + s + 8];
                float4 p3 = sp[k + s + 12];
                float d0 = fmaf(p0.x, f2x, fmaf(p0.y, f2y, fmaf(p0.z, f2z, p0.w)));
                float d1 = fmaf(p1.x, f2x, fmaf(p1.y, f2y, fmaf(p1.z, f2z, p1.w)));
                float d2 = fmaf(p2.x, f2x, fmaf(p2.y, f2y, fmaf(p2.z, f2z, p2.w)));
                float d3 = fmaf(p3.x, f2x, fmaf(p3.y, f2y, fmaf(p3.z, f2z, p3.w)));
                float mn = fminf(fminf(d0, d1), fminf(d2, d3));
                if (mn < l2) {  // rare after warm-up
                    insert3v(d0, base + k + s,      l0, l1, l2, v0, v1, v2);
                    insert3v(d1, base + k + s + 4,  l0, l1, l2, v0, v1, v2);
                    insert3v(d2, base + k + s + 8,  l0, l1, l2, v0, v1, v2);
                    insert3v(d3, base + k + s + 12, l0, l1, l2, v0, v1, v2);
                }
            }
        }
        __syncthreads();
    }

    // merge 4 lane-local sorted triples -> subgroup top-3
    float rd[3];
    int   ri[3];
    int pos = 0;
#pragma unroll
    for (int k = 0; k < 3; ++k) {
        float h  = (pos == 0) ? l0 : (pos == 1) ? l1 : (pos == 2) ? l2 : CUDART_INF_F;
        int   hi = (pos == 0) ? v0 : (pos == 1) ? v1 : (pos == 2) ? v2 : 0x7FFFFFFF;
        float mh = h; int mi = hi;
#pragma unroll
        for (int off = 1; off < 4; off <<= 1) {
            float oh = __shfl_xor_sync(0xFFFFFFFFu, mh, off);
            int   oi = __shfl_xor_sync(0xFFFFFFFFu, mi, off);
            if (oh < mh || (oh == mh && oi < mi)) { mh = oh; mi = oi; }
        }
        rd[k] = mh; ri[k] = mi;
        if (h == mh && hi == mi) ++pos;  // winning lane advances
    }

    // recompute exact squared distances for the winners; fetch original idx
    int u[3];
#pragma unroll
    for (int k = 0; k < 3; ++k) {
        if ((unsigned)ri[k] < (unsigned)kN) {
            float4 p = vp[ri[k]];
            float dx = p.x - fx, dy = p.y - fy, dz = p.z - fz;
            rd[k] = fmaf(dx, dx, fmaf(dy, dy, dz * dz));
            u[k] = __float_as_int(p.w);
        } else {
            rd[k] = CUDART_INF_F;
            u[k] = 0;
        }
    }

    float w0 = 1.0f / (rd[0] + 1e-8f);
    float w1 = 1.0f / (rd[1] + 1e-8f);
    float w2 = 1.0f / (rd[2] + 1e-8f);
    float ws = w0 + w1 + w2;
    w0 /= ws; w1 /= ws; w2 /= ws;

    // voxel bounds for this far point
    int ix = (int)floorf((fx - PCR0) / VOXS);
    int iy = (int)floorf((fy - PCR1) / VOXS);
    bool inb = active && ix >= 0 && ix < kNX && iy >= 0 && iy < kNY &&
               fz >= PCR2 && fz < PCR5;
    int seg = inb ? (iy * kNX + ix) : 0;

    if (inb) {
        const float* fb = fv + (size_t)b * kC * kN;
        float* ob = out + (size_t)b * kC * kNVOX;
#pragma unroll
        for (int k = 0; k < 8; ++k) {
            int c = s + 4 * k;
            const float* fc = fb + (size_t)c * kN;
            float val = w0 * fc[u[0]] + w1 * fc[u[1]] + w2 * fc[u[2]];
            atomicAdd(ob + (size_t)c * kNVOX + seg, val);
        }
        if (s == 0) atomicAdd(&g_cnt[(size_t)b * kNVOX + seg], 1.0f);
    }
}

// ---------------------------------------------------------------------------
// 5) sparse finalize: divide only voxels with count > 1 (identity otherwise)
// ---------------------------------------------------------------------------
__global__ void k_fin(float* __restrict__ out) {
    int i = blockIdx.x * blockDim.x + threadIdx.x;
    if (i >= kB * kNVOX) return;
    int b = i / kNVOX, v = i % kNVOX;
    float c = g_cnt[i];
    if (c > 1.0f) {
        float inv = 1.0f / c;
        float* ob = out + (size_t)b * kC * kNVOX + v;
#pragma unroll
        for (int ch = 0; ch < kC; ++ch) ob[(size_t)ch * kNVOX] *= inv;
    }
}

// ---------------------------------------------------------------------------
extern "C" void kernel_launch(void* const* d_in, const int* in_sizes, int n_in,
                              void* d_out, int out_size) {
    const float* fv   = (const float*)d_in[0];  // (B,C,H,W)
    const float* pts  = (const float*)d_in[1];  // (B,4,H,W)
    const float* ptsf = (const float*)d_in[2];  // (B,4,H,W)
    const int*   m    = (const int*)d_in[3];    // (B,H,W)
    const int*   mf   = (const int*)d_in[4];    // (B,H,W)
    float* out = (float*)d_out;                 // (B,C,NY,NX)

    k_zero<<<4096, 256>>>(out);
    k_compact<<<kB, 256>>>(pts, ptsf, m, mf);
    k_scatter_near<<<(kB * kN + 255) / 256, 256>>>(fv, pts, m, out);
    k_nn<<<kB * kN / 64, 256>>>(fv, out);
    k_fin<<<(kB * kNVOX + 255) / 256, 256>>>(out);
}

// round 4
// speedup vs baseline: 1.6183x; 1.6183x over previous
#include <cuda_runtime.h>
#include <math_constants.h>
#include <cstdint>

// Problem constants (fixed shapes from the reference)
constexpr int kB = 2;
constexpr int kC = 32;
constexpr int kH = 32;
constexpr int kW = 256;
constexpr int kN = kH * kW;            // 8192 points per batch
constexpr int kNX = 440;
constexpr int kNY = 500;
constexpr int kNVOX = kNX * kNY;       // 220000
constexpr float PCR0 = 0.0f, PCR1 = -40.0f, PCR2 = -3.0f, PCR5 = 1.0f;
constexpr float VOXS = 0.16f;

constexpr int VCH  = 4;                // candidate chunks per far point
constexpr int MAXL = 2048;             // max chunk length (= kN/VCH)

// Scratch (allocation-free: __device__ globals)
__device__ float4 g_near[kB * kN];     // compacted near pts: x,y,z, bitcast(orig idx)
__device__ float4 g_far [kB * kN];     // compacted far pts
__device__ int    g_ncnt[kB];
__device__ int    g_fcnt[kB];
__device__ float  g_cnt [kB * kNVOX];  // per-voxel point counts
__device__ float2 g_part[kB * kN * VCH * 3];  // partial top-3 (dd', idx) per chunk

// ---------------------------------------------------------------------------
// 1) zero output sums + counts (pure streaming stores)
// ---------------------------------------------------------------------------
__global__ void k_zero(float* __restrict__ out) {
    const int total  = (kB * kC * kNVOX) / 4;  // 3,520,000 float4
    const int ctotal = (kB * kNVOX) / 4;       //   110,000 float4
    float4 z = make_float4(0.f, 0.f, 0.f, 0.f);
    for (int i = blockIdx.x * blockDim.x + threadIdx.x; i < total + ctotal;
         i += gridDim.x * blockDim.x) {
        if (i < total) reinterpret_cast<float4*>(out)[i] = z;
        else           reinterpret_cast<float4*>(g_cnt)[i - total] = z;
    }
}

// ---------------------------------------------------------------------------
// 2) deterministic compaction (two-level shuffle scan, 1024 threads/block)
// ---------------------------------------------------------------------------
__device__ __forceinline__ void compact_one(const float* __restrict__ p,
                                            const int* __restrict__ mm,
                                            float4* __restrict__ dst,
                                            int* __restrict__ cnt_out,
                                            int* wsum) {
    const int t = threadIdx.x;
    const int lane = t & 31, w = t >> 5;   // 32 warps
    constexpr int PER = kN / 1024;         // 8 elements per thread

    int c = 0;
#pragma unroll
    for (int k = 0; k < PER; ++k) c += (mm[t * PER + k] > 0);

    int inc = c;
#pragma unroll
    for (int off = 1; off < 32; off <<= 1) {
        int n = __shfl_up_sync(0xFFFFFFFFu, inc, off);
        if (lane >= off) inc += n;
    }
    if (lane == 31) wsum[w] = inc;
    __syncthreads();
    if (t < 32) {
        int v = wsum[t];
        int p2 = v;
#pragma unroll
        for (int off = 1; off < 32; off <<= 1) {
            int n = __shfl_up_sync(0xFFFFFFFFu, p2, off);
            if (t >= off) p2 += n;
        }
        wsum[t] = p2 - v;              // exclusive warp offset
        if (t == 31) *cnt_out = p2;    // total
    }
    __syncthreads();
    int off = wsum[w] + inc - c;       // exclusive offset for this thread

#pragma unroll
    for (int k = 0; k < PER; ++k) {
        int n = t * PER + k;
        if (mm[n] > 0) {
            dst[off] = make_float4(p[n], p[kN + n], p[2 * kN + n],
                                   __int_as_float(n));
            ++off;
        }
    }
}

__global__ void k_compact(const float* __restrict__ pts,
                          const float* __restrict__ ptsf,
                          const int* __restrict__ m,
                          const int* __restrict__ mf) {
    __shared__ int wsum[32];
    const int b = blockIdx.x;
    compact_one(pts  + (size_t)b * 4 * kN, m  + (size_t)b * kN,
                &g_near[(size_t)b * kN], &g_ncnt[b], wsum);
    __syncthreads();
    compact_one(ptsf + (size_t)b * 4 * kN, mf + (size_t)b * kN,
                &g_far[(size_t)b * kN], &g_fcnt[b], wsum);
}

// ---------------------------------------------------------------------------
// 3) scatter valid near points into output sums + counts
// ---------------------------------------------------------------------------
__global__ void k_scatter_near(const float* __restrict__ fv,
                               const float* __restrict__ pts,
                               const int* __restrict__ m,
                               float* __restrict__ out) {
    int idx = blockIdx.x * blockDim.x + threadIdx.x;
    if (idx >= kB * kN) return;
    int b = idx / kN, n = idx % kN;
    if (m[(size_t)b * kN + n] <= 0) return;
    const float* p = pts + (size_t)b * 4 * kN;
    float x = p[n], y = p[kN + n], z = p[2 * kN + n];
    int ix = (int)floorf((x - PCR0) / VOXS);
    int iy = (int)floorf((y - PCR1) / VOXS);
    if (ix < 0 || ix >= kNX || iy < 0 || iy >= kNY || z < PCR2 || z >= PCR5) return;
    int seg = iy * kNX + ix;
    float* ob = out + (size_t)b * kC * kNVOX + seg;
    const float* f = fv + (size_t)b * kC * kN + n;
#pragma unroll
    for (int c = 0; c < kC; ++c) atomicAdd(ob + (size_t)c * kNVOX, f[(size_t)c * kN]);
    atomicAdd(&g_cnt[(size_t)b * kNVOX + seg], 1.0f);
}

// ---------------------------------------------------------------------------
// 4a) Stage A: partial 3-NN. Block = 32 far pts x 1 candidate chunk.
//     8 lanes/point; chunk staged in smem as (x,y,z,|p|^2);
//     hot loop = 3 FMA/pair; subgroup top-3 written to g_part.
// ---------------------------------------------------------------------------
__device__ __forceinline__ void insert3v(float dd, int v,
                                         float& l0, float& l1, float& l2,
                                         int& v0, int& v1, int& v2) {
    if (dd < l2) {
        if (dd < l1) {
            l2 = l1; v2 = v1;
            if (dd < l0) { l1 = l0; v1 = v0; l0 = dd; v0 = v; }
            else         { l1 = dd; v1 = v; }
        } else { l2 = dd; v2 = v; }
    }
}

__global__ void __launch_bounds__(256) k_nnA() {
    __shared__ float4 sp[MAXL];

    const int lane  = threadIdx.x & 7;
    const int sub   = threadIdx.x >> 3;          // 0..31
    const int chunk = blockIdx.x & (VCH - 1);
    const int fb    = (blockIdx.x >> 2) & 255;   // far block (32 pts each)
    const int b     = blockIdx.x >> 10;

    const int fcnt = g_fcnt[b];
    if (fb * 32 >= fcnt) return;                 // whole block idle (uniform)
    const int r = fb * 32 + sub;
    const bool active = (r < fcnt);

    const int V = g_ncnt[b];
    const int L = (V + VCH - 1) / VCH;
    const int start = chunk * L;
    int len = V - start; len = (len > L) ? L : (len < 0 ? 0 : len);
    const int Lpad = (len + 31) & ~31;

    const float4* __restrict__ vp = &g_near[(size_t)b * kN];

    for (int i = threadIdx.x; i < Lpad; i += 256) {
        float4 p;
        if (i < len) {
            p = vp[start + i];
            p.w = fmaf(p.x, p.x, fmaf(p.y, p.y, p.z * p.z));
        } else {
            p = make_float4(0.f, 0.f, 0.f, CUDART_INF_F);
        }
        sp[i] = p;
    }
    __syncthreads();

    float4 fp = g_far[(size_t)b * kN + (active ? r : 0)];
    const float f2x = -2.0f * fp.x, f2y = -2.0f * fp.y, f2z = -2.0f * fp.z;

    // lane-local top-3 on dd' = |p|^2 - 2 p.f (ordering-equivalent to d^2)
    float l0 = CUDART_INF_F, l1 = CUDART_INF_F, l2 = CUDART_INF_F;
    int   v0 = 0x7FFFFFFF,   v1 = 0x7FFFFFFF,   v2 = 0x7FFFFFFF;

    if (active) {
        for (int k = 0; k < Lpad; k += 32) {
            float4 p0 = sp[k + lane];
            float4 p1 = sp[k + lane + 8];
            float4 p2 = sp[k + lane + 16];
            float4 p3 = sp[k + lane + 24];
            float d0 = fmaf(p0.x, f2x, fmaf(p0.y, f2y, fmaf(p0.z, f2z, p0.w)));
            float d1 = fmaf(p1.x, f2x, fmaf(p1.y, f2y, fmaf(p1.z, f2z, p1.w)));
            float d2 = fmaf(p2.x, f2x, fmaf(p2.y, f2y, fmaf(p2.z, f2z, p2.w)));
            float d3 = fmaf(p3.x, f2x, fmaf(p3.y, f2y, fmaf(p3.z, f2z, p3.w)));
            float mn = fminf(fminf(d0, d1), fminf(d2, d3));
            if (mn < l2) {  // rare after warm-up
                insert3v(d0, start + k + lane,      l0, l1, l2, v0, v1, v2);
                insert3v(d1, start + k + lane + 8,  l0, l1, l2, v0, v1, v2);
                insert3v(d2, start + k + lane + 16, l0, l1, l2, v0, v1, v2);
                insert3v(d3, start + k + lane + 24, l0, l1, l2, v0, v1, v2);
            }
        }
    }

    // merge 8 lane-local sorted triples -> subgroup top-3 (all lanes join)
    float rd[3];
    int   ri[3];
    int pos = 0;
#pragma unroll
    for (int k = 0; k < 3; ++k) {
        float h  = (pos == 0) ? l0 : (pos == 1) ? l1 : (pos == 2) ? l2 : CUDART_INF_F;
        int   hi = (pos == 0) ? v0 : (pos == 1) ? v1 : (pos == 2) ? v2 : 0x7FFFFFFF;
        float mh = h; int mi = hi;
#pragma unroll
        for (int off = 1; off < 8; off <<= 1) {
            float oh = __shfl_xor_sync(0xFFFFFFFFu, mh, off);
            int   oi = __shfl_xor_sync(0xFFFFFFFFu, mi, off);
            if (oh < mh || (oh == mh && oi < mi)) { mh = oh; mi = oi; }
        }
        rd[k] = mh; ri[k] = mi;
        if (h == mh && hi == mi) ++pos;
    }

    if (active && lane == 0) {
        float2* dst = &g_part[((size_t)(b * kN + r) * VCH + chunk) * 3];
        dst[0] = make_float2(rd[0], __int_as_float(ri[0]));
        dst[1] = make_float2(rd[1], __int_as_float(ri[1]));
        dst[2] = make_float2(rd[2], __int_as_float(ri[2]));
    }
}

// ---------------------------------------------------------------------------
// 4b) Stage B: merge 4 partial triples, exact weights, gather + scatter.
//     4 lanes per far point (lane s holds chunk s's sorted triple).
// ---------------------------------------------------------------------------
__global__ void __launch_bounds__(256) k_nnB(const float* __restrict__ fv,
                                             float* __restrict__ out) {
    const int s   = threadIdx.x & 3;
    const int sub = threadIdx.x >> 2;              // 0..63
    const int b   = blockIdx.x >> 7;               // 128 blocks per batch
    const int r   = (blockIdx.x & 127) * 64 + sub;

    const int fcnt = g_fcnt[b];
    if ((blockIdx.x & 127) * 64 >= fcnt) return;   // whole block idle
    const bool active = (r < fcnt);

    float l0 = CUDART_INF_F, l1 = CUDART_INF_F, l2 = CUDART_INF_F;
    int   v0 = 0x7FFFFFFF,   v1 = 0x7FFFFFFF,   v2 = 0x7FFFFFFF;
    if (active) {
        const float2* src = &g_part[((size_t)(b * kN + r) * VCH + s) * 3];
        float2 t0 = src[0], t1 = src[1], t2 = src[2];
        l0 = t0.x; v0 = __float_as_int(t0.y);
        l1 = t1.x; v1 = __float_as_int(t1.y);
        l2 = t2.x; v2 = __float_as_int(t2.y);
    }

    // merge 4 sorted triples -> global top-3
    float rd[3];
    int   ri[3];
    int pos = 0;
#pragma unroll
    for (int k = 0; k < 3; ++k) {
        float h  = (pos == 0) ? l0 : (pos == 1) ? l1 : (pos == 2) ? l2 : CUDART_INF_F;
        int   hi = (pos == 0) ? v0 : (pos == 1) ? v1 : (pos == 2) ? v2 : 0x7FFFFFFF;
        float mh = h; int mi = hi;
#pragma unroll
        for (int off = 1; off < 4; off <<= 1) {
            float oh = __shfl_xor_sync(0xFFFFFFFFu, mh, off);
            int   oi = __shfl_xor_sync(0xFFFFFFFFu, mi, off);
            if (oh < mh || (oh == mh && oi < mi)) { mh = oh; mi = oi; }
        }
        rd[k] = mh; ri[k] = mi;
        if (h == mh && hi == mi) ++pos;
    }

    if (!active) return;  // no more shuffles/syncs below

    float4 fp = g_far[(size_t)b * kN + r];
    const float fx = fp.x, fy = fp.y, fz = fp.z;
    const float4* __restrict__ vp = &g_near[(size_t)b * kN];

    // exact squared distances for the winners; fetch original indices
    int u[3];
#pragma unroll
    for (int k = 0; k < 3; ++k) {
        if ((unsigned)ri[k] < (unsigned)kN) {
            float4 p = vp[ri[k]];
            float dx = p.x - fx, dy = p.y - fy, dz = p.z - fz;
            rd[k] = fmaf(dx, dx, fmaf(dy, dy, dz * dz));
            u[k] = __float_as_int(p.w);
        } else {
            rd[k] = CUDART_INF_F;
            u[k] = 0;
        }
    }

    float w0 = 1.0f / (rd[0] + 1e-8f);
    float w1 = 1.0f / (rd[1] + 1e-8f);
    float w2 = 1.0f / (rd[2] + 1e-8f);
    float ws = w0 + w1 + w2;
    w0 /= ws; w1 /= ws; w2 /= ws;

    int ix = (int)floorf((fx - PCR0) / VOXS);
    int iy = (int)floorf((fy - PCR1) / VOXS);
    bool inb = ix >= 0 && ix < kNX && iy >= 0 && iy < kNY &&
               fz >= PCR2 && fz < PCR5;
    if (!inb) return;
    int seg = iy * kNX + ix;

    const float* fb_ = fv + (size_t)b * kC * kN;
    float* ob = out + (size_t)b * kC * kNVOX;
#pragma unroll
    for (int k = 0; k < 8; ++k) {
        int c = s + 4 * k;
        const float* fc = fb_ + (size_t)c * kN;
        float val = w0 * fc[u[0]] + w1 * fc[u[1]] + w2 * fc[u[2]];
        atomicAdd(ob + (size_t)c * kNVOX + seg, val);
    }
    if (s == 0) atomicAdd(&g_cnt[(size_t)b * kNVOX + seg], 1.0f);
}

// ---------------------------------------------------------------------------
// 5) sparse finalize: divide only voxels with count > 1 (identity otherwise)
// ---------------------------------------------------------------------------
__global__ void k_fin(float* __restrict__ out) {
    int i = blockIdx.x * blockDim.x + threadIdx.x;
    if (i >= kB * kNVOX) return;
    int b = i / kNVOX, v = i % kNVOX;
    float c = g_cnt[i];
    if (c > 1.0f) {
        float inv = 1.0f / c;
        float* ob = out + (size_t)b * kC * kNVOX + v;
#pragma unroll
        for (int ch = 0; ch < kC; ++ch) ob[(size_t)ch * kNVOX] *= inv;
    }
}

// ---------------------------------------------------------------------------
extern "C" void kernel_launch(void* const* d_in, const int* in_sizes, int n_in,
                              void* d_out, int out_size) {
    const float* fv   = (const float*)d_in[0];  // (B,C,H,W)
    const float* pts  = (const float*)d_in[1];  // (B,4,H,W)
    const float* ptsf = (const float*)d_in[2];  // (B,4,H,W)
    const int*   m    = (const int*)d_in[3];    // (B,H,W)
    const int*   mf   = (const int*)d_in[4];    // (B,H,W)
    float* out = (float*)d_out;                 // (B,C,NY,NX)

    k_zero<<<7168, 256>>>(out);
    k_compact<<<kB, 1024>>>(pts, ptsf, m, mf);
    k_scatter_near<<<(kB * kN + 255) / 256, 256>>>(fv, pts, m, out);
    k_nnA<<<kB * 256 * VCH, 256>>>();
    k_nnB<<<kB * 128, 256>>>(fv, out);
    k_fin<<<(kB * kNVOX + 255) / 256, 256>>>(out);
}

// round 5
// speedup vs baseline: 2.1944x; 1.3560x over previous
#include <cuda_runtime.h>
#include <math_constants.h>
#include <cstdint>

// Problem constants (fixed shapes from the reference)
constexpr int kB = 2;
constexpr int kC = 32;
constexpr int kH = 32;
constexpr int kW = 256;
constexpr int kN = kH * kW;            // 8192 points per batch
constexpr int kNX = 440;
constexpr int kNY = 500;
constexpr int kNVOX = kNX * kNY;       // 220000
constexpr float PCR0 = 0.0f, PCR1 = -40.0f, PCR2 = -3.0f, PCR5 = 1.0f;
constexpr float VOXS = 0.16f;

constexpr int TILE = 2048;             // candidates per smem tile (32 KB)
constexpr int NNB_PER_B = 512;         // NN blocks per batch (16 far pts each)

// Scratch (allocation-free: __device__ globals)
__device__ float4 g_near[kB * kN];     // compacted near pts: x,y,z, bitcast(orig idx)
__device__ float4 g_far [kB * kN];     // compacted far pts
__device__ int    g_ncnt[kB];
__device__ int    g_fcnt[kB];
__device__ float  g_cnt [kB * kNVOX];  // per-voxel point counts

// ---------------------------------------------------------------------------
// compaction helper (1024 threads, two-level shuffle scan)
// ---------------------------------------------------------------------------
__device__ __forceinline__ void compact_one(const float* __restrict__ p,
                                            const int* __restrict__ mm,
                                            float4* __restrict__ dst,
                                            int* __restrict__ cnt_out,
                                            int* wsum) {
    const int t = threadIdx.x;
    const int lane = t & 31, w = t >> 5;   // 32 warps
    constexpr int PER = kN / 1024;         // 8 elements per thread

    int c = 0;
#pragma unroll
    for (int k = 0; k < PER; ++k) c += (mm[t * PER + k] > 0);

    int inc = c;
#pragma unroll
    for (int off = 1; off < 32; off <<= 1) {
        int n = __shfl_up_sync(0xFFFFFFFFu, inc, off);
        if (lane >= off) inc += n;
    }
    if (lane == 31) wsum[w] = inc;
    __syncthreads();
    if (t < 32) {
        int v = wsum[t];
        int p2 = v;
#pragma unroll
        for (int off = 1; off < 32; off <<= 1) {
            int n = __shfl_up_sync(0xFFFFFFFFu, p2, off);
            if (t >= off) p2 += n;
        }
        wsum[t] = p2 - v;              // exclusive warp offset
        if (t == 31) *cnt_out = p2;    // total
    }
    __syncthreads();
    int off = wsum[w] + inc - c;       // exclusive offset for this thread

#pragma unroll
    for (int k = 0; k < PER; ++k) {
        int n = t * PER + k;
        if (mm[n] > 0) {
            dst[off] = make_float4(p[n], p[kN + n], p[2 * kN + n],
                                   __int_as_float(n));
            ++off;
        }
    }
}

// ---------------------------------------------------------------------------
// 1) k_init: blocks 0..1 compact batch b; remaining blocks zero out + counts
// ---------------------------------------------------------------------------
__global__ void __launch_bounds__(1024) k_init(float* __restrict__ out,
                                               const float* __restrict__ pts,
                                               const float* __restrict__ ptsf,
                                               const int* __restrict__ m,
                                               const int* __restrict__ mf) {
    if (blockIdx.x < kB) {
        __shared__ int wsum[32];
        const int b = blockIdx.x;
        compact_one(pts  + (size_t)b * 4 * kN, m  + (size_t)b * kN,
                    &g_near[(size_t)b * kN], &g_ncnt[b], wsum);
        __syncthreads();
        compact_one(ptsf + (size_t)b * 4 * kN, mf + (size_t)b * kN,
                    &g_far[(size_t)b * kN], &g_fcnt[b], wsum);
        return;
    }
    const int total  = (kB * kC * kNVOX) / 4;  // 3,520,000 float4
    const int ctotal = (kB * kNVOX) / 4;       //   110,000 float4
    float4 z = make_float4(0.f, 0.f, 0.f, 0.f);
    const int nzb = gridDim.x - kB;
    for (int i = (blockIdx.x - kB) * 1024 + threadIdx.x; i < total + ctotal;
         i += nzb * 1024) {
        if (i < total) reinterpret_cast<float4*>(out)[i] = z;
        else           reinterpret_cast<float4*>(g_cnt)[i - total] = z;
    }
}

// ---------------------------------------------------------------------------
// 2) k_main
//    Blocks [0, kB*NNB_PER_B): 3-NN + interp + scatter, 16 far pts per block,
//      warp = 2 far points, 32 lanes share the candidate stream with a
//      warp-wide conservative threshold guard.
//    Blocks [kB*NNB_PER_B, +64): scatter valid near points.
// ---------------------------------------------------------------------------
__device__ __forceinline__ void insert3v(float dd, int v,
                                         float& l0, float& l1, float& l2,
                                         int& v0, int& v1, int& v2) {
    if (dd < l2) {
        if (dd < l1) {
            l2 = l1; v2 = v1;
            if (dd < l0) { l1 = l0; v1 = v0; l0 = dd; v0 = v; }
            else         { l1 = dd; v1 = v; }
        } else { l2 = dd; v2 = v; }
    }
}

__device__ __forceinline__ float warpmin(float x) {
#pragma unroll
    for (int off = 16; off > 0; off >>= 1)
        x = fminf(x, __shfl_xor_sync(0xFFFFFFFFu, x, off));
    return x;
}

// merge 32 lane-local sorted triples -> warp top-3 (ties by lower idx)
__device__ __forceinline__ void merge32(float l0, float l1, float l2,
                                        int v0, int v1, int v2,
                                        float rd[3], int ri[3]) {
    int pos = 0;
#pragma unroll
    for (int k = 0; k < 3; ++k) {
        float h  = (pos == 0) ? l0 : (pos == 1) ? l1 : (pos == 2) ? l2 : CUDART_INF_F;
        int   hi = (pos == 0) ? v0 : (pos == 1) ? v1 : (pos == 2) ? v2 : 0x7FFFFFFF;
        float mh = h; int mi = hi;
#pragma unroll
        for (int off = 16; off > 0; off >>= 1) {
            float oh = __shfl_xor_sync(0xFFFFFFFFu, mh, off);
            int   oi = __shfl_xor_sync(0xFFFFFFFFu, mi, off);
            if (oh < mh || (oh == mh && oi < mi)) { mh = oh; mi = oi; }
        }
        rd[k] = mh; ri[k] = mi;
        if (h == mh && hi == mi) ++pos;
    }
}

__global__ void __launch_bounds__(256) k_main(const float* __restrict__ fv,
                                              const float* __restrict__ pts,
                                              const int* __restrict__ m,
                                              float* __restrict__ out) {
    // ---- role: near-point scatter ----
    if (blockIdx.x >= kB * NNB_PER_B) {
        int idx = (blockIdx.x - kB * NNB_PER_B) * 256 + threadIdx.x;
        if (idx >= kB * kN) return;
        int b = idx / kN, n = idx % kN;
        if (m[(size_t)b * kN + n] <= 0) return;
        const float* p = pts + (size_t)b * 4 * kN;
        float x = p[n], y = p[kN + n], z = p[2 * kN + n];
        int ix = (int)floorf((x - PCR0) / VOXS);
        int iy = (int)floorf((y - PCR1) / VOXS);
        if (ix < 0 || ix >= kNX || iy < 0 || iy >= kNY || z < PCR2 || z >= PCR5)
            return;
        int seg = iy * kNX + ix;
        float* ob = out + (size_t)b * kC * kNVOX + seg;
        const float* f = fv + (size_t)b * kC * kN + n;
#pragma unroll
        for (int c = 0; c < kC; ++c)
            atomicAdd(ob + (size_t)c * kNVOX, f[(size_t)c * kN]);
        atomicAdd(&g_cnt[(size_t)b * kNVOX + seg], 1.0f);
        return;
    }

    // ---- role: 3-NN ----
    __shared__ float4 sp[TILE];

    const int b    = blockIdx.x / NNB_PER_B;
    const int fb   = blockIdx.x % NNB_PER_B;
    const int base = fb * 16;
    const int fcnt = g_fcnt[b];
    if (base >= fcnt) return;                    // uniform block exit

    const int lane = threadIdx.x & 31;
    const int w    = threadIdx.x >> 5;
    const int rA   = base + 2 * w;
    const int rB   = rA + 1;
    const bool activeA = (rA < fcnt);
    const bool activeB = (rB < fcnt);

    float4 fpA = g_far[(size_t)b * kN + (activeA ? rA : 0)];
    float4 fpB = g_far[(size_t)b * kN + (activeB ? rB : 0)];
    const float aX = -2.0f * fpA.x, aY = -2.0f * fpA.y, aZ = -2.0f * fpA.z;
    const float bX = -2.0f * fpB.x, bY = -2.0f * fpB.y, bZ = -2.0f * fpB.z;

    const int V = g_ncnt[b];
    const float4* __restrict__ vp = &g_near[(size_t)b * kN];

    // lane-local top-3 on dd' = |p|^2 - 2 p.f (ordering-equiv to d^2)
    float lA0 = CUDART_INF_F, lA1 = CUDART_INF_F, lA2 = CUDART_INF_F;
    int   vA0 = 0x7FFFFFFF,   vA1 = 0x7FFFFFFF,   vA2 = 0x7FFFFFFF;
    float lB0 = CUDART_INF_F, lB1 = CUDART_INF_F, lB2 = CUDART_INF_F;
    int   vB0 = 0x7FFFFFFF,   vB1 = 0x7FFFFFFF,   vB2 = 0x7FFFFFFF;
    float TmA = activeA ? CUDART_INF_F : -CUDART_INF_F;
    float TmB = activeB ? CUDART_INF_F : -CUDART_INF_F;

    int it = 0;
    for (int start = 0; start < V; start += TILE) {
        int len = V - start; len = (len > TILE) ? TILE : len;
        int Lpad = (len + 127) & ~127;
        for (int i = threadIdx.x; i < Lpad; i += 256) {
            float4 p;
            if (i < len) {
                p = vp[start + i];
                p.w = fmaf(p.x, p.x, fmaf(p.y, p.y, p.z * p.z));
            } else {
                p = make_float4(0.f, 0.f, 0.f, CUDART_INF_F);
            }
            sp[i] = p;
        }
        __syncthreads();

        for (int k = 0; k < Lpad; k += 128, ++it) {
            float4 p0 = sp[k + lane];
            float4 p1 = sp[k + lane + 32];
            float4 p2 = sp[k + lane + 64];
            float4 p3 = sp[k + lane + 96];
            float a0 = fmaf(p0.x, aX, fmaf(p0.y, aY, fmaf(p0.z, aZ, p0.w)));
            float a1 = fmaf(p1.x, aX, fmaf(p1.y, aY, fmaf(p1.z, aZ, p1.w)));
            float a2 = fmaf(p2.x, aX, fmaf(p2.y, aY, fmaf(p2.z, aZ, p2.w)));
            float a3 = fmaf(p3.x, aX, fmaf(p3.y, aY, fmaf(p3.z, aZ, p3.w)));
            float b0 = fmaf(p0.x, bX, fmaf(p0.y, bY, fmaf(p0.z, bZ, p0.w)));
            float b1 = fmaf(p1.x, bX, fmaf(p1.y, bY, fmaf(p1.z, bZ, p1.w)));
            float b2 = fmaf(p2.x, bX, fmaf(p2.y, bY, fmaf(p2.z, bZ, p2.w)));
            float b3 = fmaf(p3.x, bX, fmaf(p3.y, bY, fmaf(p3.z, bZ, p3.w)));
            float mnA = fminf(fminf(a0, a1), fminf(a2, a3));
            float mnB = fminf(fminf(b0, b1), fminf(b2, b3));
            int ci = start + k + lane;
            if (mnA < TmA) {
                insert3v(a0, ci,      lA0, lA1, lA2, vA0, vA1, vA2);
                insert3v(a1, ci + 32, lA0, lA1, lA2, vA0, vA1, vA2);
                insert3v(a2, ci + 64, lA0, lA1, lA2, vA0, vA1, vA2);
                insert3v(a3, ci + 96, lA0, lA1, lA2, vA0, vA1, vA2);
            }
            if (mnB < TmB) {
                insert3v(b0, ci,      lB0, lB1, lB2, vB0, vB1, vB2);
                insert3v(b1, ci + 32, lB0, lB1, lB2, vB0, vB1, vB2);
                insert3v(b2, ci + 64, lB0, lB1, lB2, vB0, vB1, vB2);
                insert3v(b3, ci + 96, lB0, lB1, lB2, vB0, vB1, vB2);
            }
            // refresh warp-wide conservative thresholds (stale = safe)
            if ((it & 3) == 3) {
                if (activeA) TmA = warpmin(lA2);
                if (activeB) TmB = warpmin(lB2);
            }
        }
        __syncthreads();
    }

    // merge lane lists -> warp top-3 for A and B
    float rdA[3], rdB[3];
    int riA[3], riB[3];
    merge32(lA0, lA1, lA2, vA0, vA1, vA2, rdA, riA);
    merge32(lB0, lB1, lB2, vB0, vB1, vB2, rdB, riB);

    // lanes 0-15 handle A, lanes 16-31 handle B (2 channels each)
    const bool isA = lane < 16;
    const int lh = lane & 15;
    const bool act = isA ? activeA : activeB;
    if (!act) return;

    float fx = isA ? fpA.x : fpB.x;
    float fy = isA ? fpA.y : fpB.y;
    float fz = isA ? fpA.z : fpB.z;

    float rd[3];
    int u[3];
#pragma unroll
    for (int k = 0; k < 3; ++k) {
        int r = isA ? riA[k] : riB[k];
        if ((unsigned)r < (unsigned)kN) {
            float4 p = vp[r];
            float dx = p.x - fx, dy = p.y - fy, dz = p.z - fz;
            rd[k] = fmaf(dx, dx, fmaf(dy, dy, dz * dz));
            u[k] = __float_as_int(p.w);
        } else {
            rd[k] = CUDART_INF_F;
            u[k] = 0;
        }
    }

    float w0 = 1.0f / (rd[0] + 1e-8f);
    float w1 = 1.0f / (rd[1] + 1e-8f);
    float w2 = 1.0f / (rd[2] + 1e-8f);
    float ws = w0 + w1 + w2;
    w0 /= ws; w1 /= ws; w2 /= ws;

    int ix = (int)floorf((fx - PCR0) / VOXS);
    int iy = (int)floorf((fy - PCR1) / VOXS);
    bool inb = ix >= 0 && ix < kNX && iy >= 0 && iy < kNY &&
               fz >= PCR2 && fz < PCR5;
    if (!inb) return;
    int seg = iy * kNX + ix;

    const float* fb_ = fv + (size_t)b * kC * kN;
    float* ob = out + (size_t)b * kC * kNVOX;
#pragma unroll
    for (int k = 0; k < 2; ++k) {
        int c = lh + 16 * k;
        const float* fc = fb_ + (size_t)c * kN;
        float val = w0 * fc[u[0]] + w1 * fc[u[1]] + w2 * fc[u[2]];
        atomicAdd(ob + (size_t)c * kNVOX + seg, val);
    }
    if (lh == 0) atomicAdd(&g_cnt[(size_t)b * kNVOX + seg], 1.0f);
}

// ---------------------------------------------------------------------------
// 3) sparse finalize: divide only voxels with count > 1 (identity otherwise)
// ---------------------------------------------------------------------------
__global__ void k_fin(float* __restrict__ out) {
    int i = blockIdx.x * blockDim.x + threadIdx.x;
    if (i >= kB * kNVOX) return;
    int b = i / kNVOX, v = i % kNVOX;
    float c = g_cnt[i];
    if (c > 1.0f) {
        float inv = 1.0f / c;
        float* ob = out + (size_t)b * kC * kNVOX + v;
#pragma unroll
        for (int ch = 0; ch < kC; ++ch) ob[(size_t)ch * kNVOX] *= inv;
    }
}

// ---------------------------------------------------------------------------
extern "C" void kernel_launch(void* const* d_in, const int* in_sizes, int n_in,
                              void* d_out, int out_size) {
    const float* fv   = (const float*)d_in[0];  // (B,C,H,W)
    const float* pts  = (const float*)d_in[1];  // (B,4,H,W)
    const float* ptsf = (const float*)d_in[2];  // (B,4,H,W)
    const int*   m    = (const int*)d_in[3];    // (B,H,W)
    const int*   mf   = (const int*)d_in[4];    // (B,H,W)
    float* out = (float*)d_out;                 // (B,C,NY,NX)

    k_init<<<kB + 1024, 1024>>>(out, pts, ptsf, m, mf);
    k_main<<<kB * NNB_PER_B + (kB * kN) / 256, 256>>>(fv, pts, m, out);
    k_fin<<<(kB * kNVOX + 255) / 256, 256>>>(out);
}